// round 13
// baseline (speedup 1.0000x reference)
#include <cuda_runtime.h>
#include <cuda_bf16.h>
#include <stdint.h>
#include <math.h>

// ---------------- problem constants ----------------
#define BATCH 2048
#define NC    4
#define NRIS  100
#define DIN   303
#define D1    1024
#define D2    1024
#define D3    512
#define DOUT  264
#define INV_THRESH 1.0e15f

#define KP1 320
#define KP2 1024
#define KP3 1024
#define KP4 512

// ---------------- scratch ----------------
__device__ float g_t1[BATCH * DOUT];
__device__ float g_thetaN[BATCH * 2 * NRIS];
__device__ float g_ccc[BATCH * NC];

// split activations (hi/lo bf16)
__device__ __nv_bfloat16 g_Xh[BATCH * KP1], g_Xl[BATCH * KP1];
__device__ __nv_bfloat16 g_h1h[BATCH * D1], g_h1l[BATCH * D1];
__device__ __nv_bfloat16 g_h2h[BATCH * D2], g_h2l[BATCH * D2];
__device__ __nv_bfloat16 g_h3h[BATCH * D3], g_h3l[BATCH * D3];

// split weights, transposed to [N, Kp] bf16, hi/lo parts
__device__ __nv_bfloat16 g_W1h[D1 * KP1], g_W1l[D1 * KP1];
__device__ __nv_bfloat16 g_W2h[D2 * KP2], g_W2l[D2 * KP2];
__device__ __nv_bfloat16 g_W3h[D3 * KP3], g_W3l[D3 * KP3];
__device__ __nv_bfloat16 g_W4h[DOUT * KP4], g_W4l[DOUT * KP4];

// ---------------- low-level helpers ----------------
__device__ __forceinline__ uint32_t s2u(const void* p) {
    uint32_t a;
    asm("{ .reg .u64 t; cvta.to.shared.u64 t, %1; cvt.u32.u64 %0, t; }"
        : "=r"(a) : "l"(p));
    return a;
}
__device__ __forceinline__ void ldsm_x4(uint32_t* r, uint32_t addr) {
    asm volatile("ldmatrix.sync.aligned.m8n8.x4.shared.b16 {%0,%1,%2,%3}, [%4];"
                 : "=r"(r[0]), "=r"(r[1]), "=r"(r[2]), "=r"(r[3]) : "r"(addr));
}
__device__ __forceinline__ void mma16816(float* d, const uint32_t* a,
                                         const uint32_t* b) {
    asm volatile(
        "mma.sync.aligned.m16n8k16.row.col.f32.bf16.bf16.f32 "
        "{%0,%1,%2,%3}, {%4,%5,%6,%7}, {%8,%9}, {%0,%1,%2,%3};"
        : "+f"(d[0]), "+f"(d[1]), "+f"(d[2]), "+f"(d[3])
        : "r"(a[0]), "r"(a[1]), "r"(a[2]), "r"(a[3]), "r"(b[0]), "r"(b[1]));
}
__device__ __forceinline__ void cp16(uint32_t dst, const void* src, bool pred) {
    int sz = pred ? 16 : 0;
    asm volatile("cp.async.cg.shared.global [%0], [%1], 16, %2;"
                 :: "r"(dst), "l"(src), "r"(sz));
}
#define CP_COMMIT() asm volatile("cp.async.commit_group;" ::: "memory")
#define CP_WAIT(n)  asm volatile("cp.async.wait_group %0;" :: "n"(n) : "memory")

__device__ __forceinline__ uint32_t pack_bf16(float lo, float hi) {
    uint32_t r;
    asm("cvt.rn.bf16x2.f32 %0, %1, %2;" : "=r"(r) : "f"(hi), "f"(lo));
    return r;
}
// SW64 swizzle for 64-byte rows (BK=32 bf16)
#define SWZ64(b) ((b) ^ (((b) >> 3) & 0x30))

// ---------------- fused weight transpose + bf16 split -----------------------
#define NBX1 (KP1 / 32)
#define NBX2 (KP2 / 32)
#define NBX3 (KP3 / 32)
#define NBX4 (KP4 / 32)
#define NB1 (NBX1 * ((D1 + 31) / 32))
#define NB2 (NBX2 * ((D2 + 31) / 32))
#define NB3 (NBX3 * ((D3 + 31) / 32))
#define NB4 (NBX4 * ((DOUT + 31) / 32))
#define NB_TOTAL (NB1 + NB2 + NB3 + NB4)

__global__ __launch_bounds__(256) void split_transpose_all(
    const float* __restrict__ W1a, const float* __restrict__ W2a,
    const float* __restrict__ W3a, const float* __restrict__ W4a,
    __nv_bfloat16* __restrict__ h1, __nv_bfloat16* __restrict__ l1,
    __nv_bfloat16* __restrict__ h2, __nv_bfloat16* __restrict__ l2,
    __nv_bfloat16* __restrict__ h3, __nv_bfloat16* __restrict__ l3,
    __nv_bfloat16* __restrict__ h4, __nv_bfloat16* __restrict__ l4)
{
    int bid = blockIdx.x;
    const float* W; __nv_bfloat16 *Wh, *Wl;
    int K, N, Kp, nbx, r;
    if (bid < NB1) {
        W = W1a; Wh = h1; Wl = l1; K = DIN; N = D1; Kp = KP1; nbx = NBX1; r = bid;
    } else if (bid < NB1 + NB2) {
        W = W2a; Wh = h2; Wl = l2; K = D1; N = D2; Kp = KP2; nbx = NBX2; r = bid - NB1;
    } else if (bid < NB1 + NB2 + NB3) {
        W = W3a; Wh = h3; Wl = l3; K = D2; N = D3; Kp = KP3; nbx = NBX3; r = bid - NB1 - NB2;
    } else {
        W = W4a; Wh = h4; Wl = l4; K = D3; N = DOUT; Kp = KP4; nbx = NBX4; r = bid - NB1 - NB2 - NB3;
    }
    int k0 = (r % nbx) * 32, n0 = (r / nbx) * 32;

    __shared__ float tile[32][33];
    int tx = threadIdx.x % 32, ty = threadIdx.x / 32;
#pragma unroll
    for (int i = 0; i < 4; i++) {
        int k = k0 + ty + i * 8, n = n0 + tx;
        tile[ty + i * 8][tx] = (k < K && n < N) ? W[(size_t)k * N + n] : 0.f;
    }
    __syncthreads();
#pragma unroll
    for (int i = 0; i < 4; i++) {
        int n = n0 + ty + i * 8, k = k0 + tx;
        if (n < N) {
            float v = tile[tx][ty + i * 8];
            __nv_bfloat16 h = __float2bfloat16(v);
            float rr = v - __bfloat162float(h);
            Wh[(size_t)n * Kp + k] = h;
            Wl[(size_t)n * Kp + k] = __float2bfloat16(rr);
        }
    }
}

// ---------------- input split: X fp32 [B,DIN] -> Xh/Xl [B,KP1] bf16 ---------
__global__ __launch_bounds__(256) void split_input(
    const float* __restrict__ X,
    __nv_bfloat16* __restrict__ Xh, __nv_bfloat16* __restrict__ Xl)
{
    int idx = blockIdx.x * 256 + threadIdx.x;
    if (idx >= BATCH * KP1) return;
    int b = idx / KP1, k = idx - b * KP1;
    float v = (k < DIN) ? X[(size_t)b * DIN + k] : 0.f;
    __nv_bfloat16 h = __float2bfloat16(v);
    float r = v - __bfloat162float(h);
    Xh[idx] = h;
    Xl[idx] = __float2bfloat16(r);
}

// ---------------- mma.sync bf16-split GEMM (wide warp tiles) -----------------
// C = relu?(A @ W^T + bias). A split bf16 (Ah, Al) [M,Kp] K-major.
// BM=64, BN=128, BK=32. 128 threads = 4 warps (2M x 2N), warp tile 32x64.
// 4 CTAs/SM. 3-pass: AhBh + AlBh + AhBl. Double-buffered cp.async, SW64.
#define A1BYTES 4096                        // one A buffer (64 rows x 64B)
#define B1BYTES 8192                        // one B buffer (128 rows x 64B)
#define QSTAGE  (2 * A1BYTES + 2 * B1BYTES) // 24576
#define SMEM_GEMM (2 * QSTAGE)              // 49152

__global__ __launch_bounds__(128, 4) void gemm_mma(
    const __nv_bfloat16* __restrict__ Ah,
    const __nv_bfloat16* __restrict__ Al,
    const __nv_bfloat16* __restrict__ Wh,
    const __nv_bfloat16* __restrict__ Wl,
    const float* __restrict__ bias,
    float* __restrict__ Cf,
    __nv_bfloat16* __restrict__ Ch, __nv_bfloat16* __restrict__ Cl,
    int M, int N, int Kp, int relu, int outf32)
{
    constexpr int NT = 8;   // 8-col tiles per warp (64 cols)

    extern __shared__ char smem[];
    const uint32_t sb = s2u(smem);
    const int tid  = threadIdx.x;
    const int lane = tid & 31;
    const int wid  = tid >> 5;
    const int wm   = wid & 1;     // 0..1 -> 32*wm
    const int wn   = wid >> 1;    // 0..1 -> 64*wn
    const int m0 = blockIdx.y * 64;
    const int n0 = blockIdx.x * 128;
    const int nch = Kp >> 5;      // BK=32

    float acc[2][NT][4];
#pragma unroll
    for (int mt = 0; mt < 2; mt++)
#pragma unroll
        for (int nt = 0; nt < NT; nt++)
#pragma unroll
            for (int e = 0; e < 4; e++) acc[mt][nt][e] = 0.f;

    auto stageA = [&](int c) {
        const uint32_t s = (uint32_t)(c & 1) * QSTAGE;
        const int kk0 = c * 32;
#pragma unroll
        for (int g = 0; g < 2; g++) {
            int idx = tid + g * 128;
            int m = idx >> 2, j = idx & 3;     // row, 16B chunk
            uint32_t sw = SWZ64((uint32_t)(m * 64 + j * 16));
            const size_t off = (size_t)(m0 + m) * Kp + kk0 + j * 8;
            cp16(sb + s + sw,           Ah + off, true);
            cp16(sb + s + A1BYTES + sw, Al + off, true);
        }
    };
    auto stageB = [&](int c) {
        const uint32_t s = (uint32_t)(c & 1) * QSTAGE;
        const int kk0 = c * 32;
#pragma unroll
        for (int g = 0; g < 4; g++) {
            int idx = tid + g * 128;
            int n = idx >> 2, j = idx & 3;
            bool ok = (n0 + n) < N;
            int row = ok ? (n0 + n) : 0;
            uint32_t sw = SWZ64((uint32_t)(n * 64 + j * 16));
            const size_t off = (size_t)row * Kp + kk0 + j * 8;
            cp16(sb + s + 2 * A1BYTES + sw,           Wh + off, ok);
            cp16(sb + s + 2 * A1BYTES + B1BYTES + sw, Wl + off, ok);
        }
    };

    const int qa = lane >> 3;
    const uint32_t rowA  = (uint32_t)(wm * 32 + (qa & 1) * 8 + (lane & 7));
    const uint32_t kaOff = (uint32_t)((qa >> 1) * 16);
    // paired-B ldmatrix.x4 lane map: 2 n-tiles x 2 k-halves
    const uint32_t rowBp = (uint32_t)(wn * 64 + ((lane >> 4) & 1) * 8 + (lane & 7));
    const uint32_t kbOff = (uint32_t)(((lane >> 3) & 1) * 16);

    auto compute = [&](int c) {
        const uint32_t s = (uint32_t)(c & 1) * QSTAGE;
        const uint32_t bAh = sb + s, bAl = sb + s + A1BYTES;
        const uint32_t bBh = sb + s + 2 * A1BYTES, bBl = bBh + B1BYTES;
#pragma unroll
        for (int s16 = 0; s16 < 2; s16++) {
            uint32_t a_h[2][4], a_l[2][4];
#pragma unroll
            for (int mt = 0; mt < 2; mt++) {
                uint32_t off = SWZ64((rowA + mt * 16) * 64 + s16 * 32 + kaOff);
                ldsm_x4(a_h[mt], bAh + off);
                ldsm_x4(a_l[mt], bAl + off);
            }
            // b_h: 8 n-tiles via 4 paired ldsm_x4
            uint32_t b_h[NT][2];
#pragma unroll
            for (int ntp = 0; ntp < NT / 2; ntp++) {
                uint32_t off = SWZ64((rowBp + ntp * 16) * 64 + s16 * 32 + kbOff);
                uint32_t r4[4];
                ldsm_x4(r4, bBh + off);
                b_h[2 * ntp][0] = r4[0]; b_h[2 * ntp][1] = r4[1];
                b_h[2 * ntp + 1][0] = r4[2]; b_h[2 * ntp + 1][1] = r4[3];
            }
            // passes 1 & 2 consume b_h, then b_h is dead
#pragma unroll
            for (int mt = 0; mt < 2; mt++)
#pragma unroll
                for (int nt = 0; nt < NT; nt++) {
                    mma16816(acc[mt][nt], a_h[mt], b_h[nt]);
                    mma16816(acc[mt][nt], a_l[mt], b_h[nt]);
                }
            // pass 3: load b_l late (short liveness) and consume
            uint32_t b_l[NT][2];
#pragma unroll
            for (int ntp = 0; ntp < NT / 2; ntp++) {
                uint32_t off = SWZ64((rowBp + ntp * 16) * 64 + s16 * 32 + kbOff);
                uint32_t r4[4];
                ldsm_x4(r4, bBl + off);
                b_l[2 * ntp][0] = r4[0]; b_l[2 * ntp][1] = r4[1];
                b_l[2 * ntp + 1][0] = r4[2]; b_l[2 * ntp + 1][1] = r4[3];
            }
#pragma unroll
            for (int mt = 0; mt < 2; mt++)
#pragma unroll
                for (int nt = 0; nt < NT; nt++)
                    mma16816(acc[mt][nt], a_h[mt], b_l[nt]);
        }
    };

    stageA(0); stageB(0); CP_COMMIT();

    for (int c = 0; c < nch; c++) {
        if (c + 1 < nch) {
            stageA(c + 1); stageB(c + 1); CP_COMMIT();
            CP_WAIT(1);
        } else {
            CP_WAIT(0);
        }
        __syncthreads();
        compute(c);
        __syncthreads();
    }

    // ---- epilogue ----
#pragma unroll
    for (int mt = 0; mt < 2; mt++) {
        int r0 = m0 + wm * 32 + mt * 16 + (lane >> 2);
#pragma unroll
        for (int nt = 0; nt < NT; nt++) {
            int col = n0 + wn * 64 + nt * 8 + (lane & 3) * 2;
            if (col >= N) continue;
            float2 bv = *(const float2*)(bias + col);
            float o0 = acc[mt][nt][0] + bv.x;
            float o1 = acc[mt][nt][1] + bv.y;
            float o2 = acc[mt][nt][2] + bv.x;
            float o3 = acc[mt][nt][3] + bv.y;
            if (relu) {
                o0 = fmaxf(o0, 0.f); o1 = fmaxf(o1, 0.f);
                o2 = fmaxf(o2, 0.f); o3 = fmaxf(o3, 0.f);
            }
            if (outf32) {
                *(float2*)(Cf + (size_t)r0 * N + col)       = make_float2(o0, o1);
                *(float2*)(Cf + (size_t)(r0 + 8) * N + col) = make_float2(o2, o3);
            } else {
                __nv_bfloat16 h0 = __float2bfloat16(o0);
                __nv_bfloat16 h1 = __float2bfloat16(o1);
                __nv_bfloat16 h2 = __float2bfloat16(o2);
                __nv_bfloat16 h3 = __float2bfloat16(o3);
                uint32_t hp0 = (uint32_t)__bfloat16_as_ushort(h0) |
                               ((uint32_t)__bfloat16_as_ushort(h1) << 16);
                uint32_t hp1 = (uint32_t)__bfloat16_as_ushort(h2) |
                               ((uint32_t)__bfloat16_as_ushort(h3) << 16);
                uint32_t lp0 = pack_bf16(o0 - __bfloat162float(h0),
                                         o1 - __bfloat162float(h1));
                uint32_t lp1 = pack_bf16(o2 - __bfloat162float(h2),
                                         o3 - __bfloat162float(h3));
                *(uint32_t*)(Ch + (size_t)r0 * N + col)       = hp0;
                *(uint32_t*)(Ch + (size_t)(r0 + 8) * N + col) = hp1;
                *(uint32_t*)(Cl + (size_t)r0 * N + col)       = lp0;
                *(uint32_t*)(Cl + (size_t)(r0 + 8) * N + col) = lp1;
            }
        }
    }
}

// ---------------- postprocess: unit-modulus theta + precoder normalization --
__global__ __launch_bounds__(128) void postproc_kernel(
    const float* __restrict__ t1, float* __restrict__ thetaN,
    float* __restrict__ out)
{
    const int b   = blockIdx.x;
    const int tid = threadIdx.x;
    const float* row  = t1  + (size_t)b * DOUT;
    float*       orow = out + (size_t)b * DOUT;

    __shared__ float s[2];

    if (tid < NRIS) {
        float re = row[tid];
        float im = row[NRIS + tid];
        float inv = rsqrtf(re * re + im * im);
        thetaN[(size_t)b * 200 + tid]       = re * inv;
        thetaN[(size_t)b * 200 + 100 + tid] = im * inv;
    }

    int w = tid >> 5, l = tid & 31;
    if (w < 2) {
        int base = 200 + 32 * w;
        float v = 0.f;
        if (l < 16) {
            float re = row[base + l];
            float im = row[base + 16 + l];
            v = re * re + im * im;
        }
#pragma unroll
        for (int o = 8; o; o >>= 1) v += __shfl_down_sync(0xffffffffu, v, o);
        if (l == 0) s[w] = sqrtf(2.0f / v);
    }
    __syncthreads();

    if (tid < 64) {
        int col  = 200 + tid;
        float sc = (tid < 32) ? s[0] : s[1];
        orow[col] = row[col] * sc;
    }
}

// ---------------- quad pass 1: CCC[b][c] = Re(theta^H T_c theta)/thr --------
__global__ __launch_bounds__(256) void quad_pass1(
    const float* __restrict__ Tr, const float* __restrict__ Ti,
    const float* __restrict__ thetaN, float* __restrict__ ccc)
{
    const int bc = blockIdx.x;
    const int b  = bc >> 2;
    const int tid = threadIdx.x;

    __shared__ float sa[100], sb_[100];
    __shared__ float da[4][32], db[4][32];
    __shared__ float wsum[8];

    if (tid < 200) {
        float v = thetaN[(size_t)b * 200 + tid];
        if (tid < 100) {
            sa[tid] = v;
            da[tid & 3][tid >> 2] = v;
        } else {
            int t = tid - 100;
            sb_[t] = v;
            db[t & 3][t >> 2] = v;
        }
    }
    __syncthreads();

    const float4* TrV = (const float4*)(Tr + (size_t)bc * 10000);
    const float4* TiV = (const float4*)(Ti + (size_t)bc * 10000);

    float acc = 0.f;
    for (int i = tid; i < 2500; i += 256) {
        int n = i / 25;
        int q = i - n * 25;
        float4 tr = __ldcs(TrV + i);
        float4 ti = __ldcs(TiV + i);
        float an = sa[n], bn = sb_[n];
        {
            float am = da[0][q], bm = db[0][q];
            acc += tr.x * (an * am + bn * bm) + ti.x * (bn * am - an * bm);
        }
        {
            float am = da[1][q], bm = db[1][q];
            acc += tr.y * (an * am + bn * bm) + ti.y * (bn * am - an * bm);
        }
        {
            float am = da[2][q], bm = db[2][q];
            acc += tr.z * (an * am + bn * bm) + ti.z * (bn * am - an * bm);
        }
        {
            float am = da[3][q], bm = db[3][q];
            acc += tr.w * (an * am + bn * bm) + ti.w * (bn * am - an * bm);
        }
    }

#pragma unroll
    for (int o = 16; o; o >>= 1) acc += __shfl_down_sync(0xffffffffu, acc, o);
    if ((tid & 31) == 0) wsum[tid >> 5] = acc;
    __syncthreads();
    if (tid == 0) {
        float s = 0.f;
#pragma unroll
        for (int w = 0; w < 8; w++) s += wsum[w];
        ccc[bc] = s * INV_THRESH;
    }
}

// ---------------- quad pass 2: scale + write theta_hat ----------------------
__global__ __launch_bounds__(256) void quad_pass2(
    const float* __restrict__ ccc, const float* __restrict__ thetaN,
    float* __restrict__ out)
{
    const int b = blockIdx.x;
    const int tid = threadIdx.x;
    float c0 = ccc[b * 4 + 0], c1 = ccc[b * 4 + 1];
    float c2 = ccc[b * 4 + 2], c3 = ccc[b * 4 + 3];
    float mx = fmaxf(fmaxf(c0, c1), fmaxf(c2, c3));
    float scale = rsqrtf(fmaxf(mx, 1.0f));
    if (tid < 200)
        out[(size_t)b * DOUT + tid] = thetaN[(size_t)b * 200 + tid] * scale;
}

// ---------------- launch ----------------------------------------------------
extern "C" void kernel_launch(void* const* d_in, const int* in_sizes, int n_in,
                              void* d_out, int out_size)
{
    const float* X  = (const float*)d_in[0];
    const float* Tr = (const float*)d_in[1];
    const float* Ti = (const float*)d_in[2];
    const float* W1 = (const float*)d_in[3];
    const float* b1 = (const float*)d_in[4];
    const float* W2 = (const float*)d_in[5];
    const float* b2 = (const float*)d_in[6];
    const float* W3 = (const float*)d_in[7];
    const float* b3 = (const float*)d_in[8];
    const float* W4 = (const float*)d_in[9];
    const float* b4 = (const float*)d_in[10];
    float* out = (float*)d_out;

    float *t1, *thN, *ccc;
    cudaGetSymbolAddress((void**)&t1,  g_t1);
    cudaGetSymbolAddress((void**)&thN, g_thetaN);
    cudaGetSymbolAddress((void**)&ccc, g_ccc);

    __nv_bfloat16 *xh, *xl, *h1h, *h1l, *h2h, *h2l, *h3h, *h3l;
    cudaGetSymbolAddress((void**)&xh,  g_Xh);
    cudaGetSymbolAddress((void**)&xl,  g_Xl);
    cudaGetSymbolAddress((void**)&h1h, g_h1h);
    cudaGetSymbolAddress((void**)&h1l, g_h1l);
    cudaGetSymbolAddress((void**)&h2h, g_h2h);
    cudaGetSymbolAddress((void**)&h2l, g_h2l);
    cudaGetSymbolAddress((void**)&h3h, g_h3h);
    cudaGetSymbolAddress((void**)&h3l, g_h3l);

    __nv_bfloat16 *w1h, *w1l, *w2h, *w2l, *w3h, *w3l, *w4h, *w4l;
    cudaGetSymbolAddress((void**)&w1h, g_W1h);
    cudaGetSymbolAddress((void**)&w1l, g_W1l);
    cudaGetSymbolAddress((void**)&w2h, g_W2h);
    cudaGetSymbolAddress((void**)&w2l, g_W2l);
    cudaGetSymbolAddress((void**)&w3h, g_W3h);
    cudaGetSymbolAddress((void**)&w3l, g_W3l);
    cudaGetSymbolAddress((void**)&w4h, g_W4h);
    cudaGetSymbolAddress((void**)&w4l, g_W4l);

    cudaFuncSetAttribute(gemm_mma, cudaFuncAttributeMaxDynamicSharedMemorySize,
                         SMEM_GEMM);

    split_transpose_all<<<NB_TOTAL, 256>>>(W1, W2, W3, W4,
                                           w1h, w1l, w2h, w2l,
                                           w3h, w3l, w4h, w4l);
    split_input<<<(BATCH * KP1 + 255) / 256, 256>>>(X, xh, xl);

    gemm_mma<<<dim3(D1 / 128, BATCH / 64), 128, SMEM_GEMM>>>(
        xh, xl, w1h, w1l, b1, nullptr, h1h, h1l, BATCH, D1, KP1, 1, 0);
    gemm_mma<<<dim3(D2 / 128, BATCH / 64), 128, SMEM_GEMM>>>(
        h1h, h1l, w2h, w2l, b2, nullptr, h2h, h2l, BATCH, D2, KP2, 1, 0);
    gemm_mma<<<dim3(D3 / 128, BATCH / 64), 128, SMEM_GEMM>>>(
        h2h, h2l, w3h, w3l, b3, nullptr, h3h, h3l, BATCH, D3, KP3, 1, 0);
    gemm_mma<<<dim3((DOUT + 127) / 128, BATCH / 64), 128, SMEM_GEMM>>>(
        h3h, h3l, w4h, w4l, b4, t1, nullptr, nullptr, BATCH, DOUT, KP4, 0, 1);

    postproc_kernel<<<BATCH, 128>>>(t1, thN, out);
    quad_pass1<<<BATCH * NC, 256>>>(Tr, Ti, thN, ccc);
    quad_pass2<<<BATCH, 256>>>(ccc, thN, out);
}

// round 14
// speedup vs baseline: 1.4356x; 1.4356x over previous
#include <cuda_runtime.h>
#include <cuda_bf16.h>
#include <stdint.h>
#include <math.h>

// ---------------- problem constants ----------------
#define BATCH 2048
#define NC    4
#define NRIS  100
#define DIN   303
#define D1    1024
#define D2    1024
#define D3    512
#define DOUT  264
#define INV_THRESH 1.0e15f

#define KP1 320
#define KP2 1024
#define KP3 1024
#define KP4 512

// ---------------- scratch ----------------
__device__ float g_t1[BATCH * DOUT];
__device__ float g_ccc[BATCH * NC];

// split activations (hi/lo bf16)
__device__ __nv_bfloat16 g_Xh[BATCH * KP1], g_Xl[BATCH * KP1];
__device__ __nv_bfloat16 g_h1h[BATCH * D1], g_h1l[BATCH * D1];
__device__ __nv_bfloat16 g_h2h[BATCH * D2], g_h2l[BATCH * D2];
__device__ __nv_bfloat16 g_h3h[BATCH * D3], g_h3l[BATCH * D3];

// split weights, transposed to [N, Kp] bf16, hi/lo parts
__device__ __nv_bfloat16 g_W1h[D1 * KP1], g_W1l[D1 * KP1];
__device__ __nv_bfloat16 g_W2h[D2 * KP2], g_W2l[D2 * KP2];
__device__ __nv_bfloat16 g_W3h[D3 * KP3], g_W3l[D3 * KP3];
__device__ __nv_bfloat16 g_W4h[DOUT * KP4], g_W4l[DOUT * KP4];

// ---------------- low-level helpers ----------------
__device__ __forceinline__ uint32_t s2u(const void* p) {
    uint32_t a;
    asm("{ .reg .u64 t; cvta.to.shared.u64 t, %1; cvt.u32.u64 %0, t; }"
        : "=r"(a) : "l"(p));
    return a;
}
__device__ __forceinline__ void ldsm_x4(uint32_t* r, uint32_t addr) {
    asm volatile("ldmatrix.sync.aligned.m8n8.x4.shared.b16 {%0,%1,%2,%3}, [%4];"
                 : "=r"(r[0]), "=r"(r[1]), "=r"(r[2]), "=r"(r[3]) : "r"(addr));
}
__device__ __forceinline__ void mma16816(float* d, const uint32_t* a,
                                         const uint32_t* b) {
    asm volatile(
        "mma.sync.aligned.m16n8k16.row.col.f32.bf16.bf16.f32 "
        "{%0,%1,%2,%3}, {%4,%5,%6,%7}, {%8,%9}, {%0,%1,%2,%3};"
        : "+f"(d[0]), "+f"(d[1]), "+f"(d[2]), "+f"(d[3])
        : "r"(a[0]), "r"(a[1]), "r"(a[2]), "r"(a[3]), "r"(b[0]), "r"(b[1]));
}
__device__ __forceinline__ void cp16(uint32_t dst, const void* src, bool pred) {
    int sz = pred ? 16 : 0;
    asm volatile("cp.async.cg.shared.global [%0], [%1], 16, %2;"
                 :: "r"(dst), "l"(src), "r"(sz));
}
#define CP_COMMIT() asm volatile("cp.async.commit_group;" ::: "memory")
#define CP_WAIT(n)  asm volatile("cp.async.wait_group %0;" :: "n"(n) : "memory")

__device__ __forceinline__ uint32_t pack_bf16(float lo, float hi) {
    uint32_t r;
    asm("cvt.rn.bf16x2.f32 %0, %1, %2;" : "=r"(r) : "f"(hi), "f"(lo));
    return r;
}
#define SWZ(b) ((b) ^ (((b) >> 3) & 0x70))

// ---------------- fused prep: weight transpose+split AND input split --------
#define NBX1 (KP1 / 32)
#define NBX2 (KP2 / 32)
#define NBX3 (KP3 / 32)
#define NBX4 (KP4 / 32)
#define NB1 (NBX1 * ((D1 + 31) / 32))
#define NB2 (NBX2 * ((D2 + 31) / 32))
#define NB3 (NBX3 * ((D3 + 31) / 32))
#define NB4 (NBX4 * ((DOUT + 31) / 32))
#define NB_W (NB1 + NB2 + NB3 + NB4)
#define NB_X ((BATCH * KP1 + 255) / 256)
#define NB_TOTAL (NB_W + NB_X)

__global__ __launch_bounds__(256) void prep_all(
    const float* __restrict__ X,
    const float* __restrict__ W1a, const float* __restrict__ W2a,
    const float* __restrict__ W3a, const float* __restrict__ W4a,
    __nv_bfloat16* __restrict__ xh, __nv_bfloat16* __restrict__ xl,
    __nv_bfloat16* __restrict__ h1, __nv_bfloat16* __restrict__ l1,
    __nv_bfloat16* __restrict__ h2, __nv_bfloat16* __restrict__ l2,
    __nv_bfloat16* __restrict__ h3, __nv_bfloat16* __restrict__ l3,
    __nv_bfloat16* __restrict__ h4, __nv_bfloat16* __restrict__ l4)
{
    int bid = blockIdx.x;
    if (bid >= NB_W) {
        // input split: X fp32 [B,DIN] -> Xh/Xl [B,KP1]
        int idx = (bid - NB_W) * 256 + threadIdx.x;
        if (idx < BATCH * KP1) {
            int b = idx / KP1, k = idx - b * KP1;
            float v = (k < DIN) ? X[(size_t)b * DIN + k] : 0.f;
            __nv_bfloat16 h = __float2bfloat16(v);
            float r = v - __bfloat162float(h);
            xh[idx] = h;
            xl[idx] = __float2bfloat16(r);
        }
        return;
    }

    const float* W; __nv_bfloat16 *Wh, *Wl;
    int K, N, Kp, nbx, r;
    if (bid < NB1) {
        W = W1a; Wh = h1; Wl = l1; K = DIN; N = D1; Kp = KP1; nbx = NBX1; r = bid;
    } else if (bid < NB1 + NB2) {
        W = W2a; Wh = h2; Wl = l2; K = D1; N = D2; Kp = KP2; nbx = NBX2; r = bid - NB1;
    } else if (bid < NB1 + NB2 + NB3) {
        W = W3a; Wh = h3; Wl = l3; K = D2; N = D3; Kp = KP3; nbx = NBX3; r = bid - NB1 - NB2;
    } else {
        W = W4a; Wh = h4; Wl = l4; K = D3; N = DOUT; Kp = KP4; nbx = NBX4; r = bid - NB1 - NB2 - NB3;
    }
    int k0 = (r % nbx) * 32, n0 = (r / nbx) * 32;

    __shared__ float tile[32][33];
    int tx = threadIdx.x % 32, ty = threadIdx.x / 32;
#pragma unroll
    for (int i = 0; i < 4; i++) {
        int k = k0 + ty + i * 8, n = n0 + tx;
        tile[ty + i * 8][tx] = (k < K && n < N) ? W[(size_t)k * N + n] : 0.f;
    }
    __syncthreads();
#pragma unroll
    for (int i = 0; i < 4; i++) {
        int n = n0 + ty + i * 8, k = k0 + tx;
        if (n < N) {
            float v = tile[tx][ty + i * 8];
            __nv_bfloat16 h = __float2bfloat16(v);
            float rr = v - __bfloat162float(h);
            Wh[(size_t)n * Kp + k] = h;
            Wl[(size_t)n * Kp + k] = __float2bfloat16(rr);
        }
    }
}

// ---------------- mma.sync bf16-split GEMM (round-9 proven config) ----------
// C = relu?(A @ W^T + bias). A split bf16 (Ah, Al) [M,Kp] K-major.
// BM=64, BN=128, BK=64. 8 warps: 2M x 4N, warp tile 32x32. 2 CTAs/SM.
// 3-pass: AhBh + AlBh + AhBl. Double-buffered cp.async, SW128.
#define ABYTES 8192
#define BBYTES 16384
#define STAGE  (2 * ABYTES + 2 * BBYTES)
#define SMEM_GEMM (2 * STAGE)

__global__ __launch_bounds__(256, 2) void gemm_mma(
    const __nv_bfloat16* __restrict__ Ah,
    const __nv_bfloat16* __restrict__ Al,
    const __nv_bfloat16* __restrict__ Wh,
    const __nv_bfloat16* __restrict__ Wl,
    const float* __restrict__ bias,
    float* __restrict__ Cf,
    __nv_bfloat16* __restrict__ Ch, __nv_bfloat16* __restrict__ Cl,
    int M, int N, int Kp, int relu, int outf32)
{
    constexpr int NT = 4;

    extern __shared__ char smem[];
    const uint32_t sb = s2u(smem);
    const int tid  = threadIdx.x;
    const int lane = tid & 31;
    const int wid  = tid >> 5;
    const int wm   = wid & 1;
    const int wn   = wid >> 1;
    const int m0 = blockIdx.y * 64;
    const int n0 = blockIdx.x * 128;
    const int nch = Kp >> 6;

    float acc[2][NT][4];
#pragma unroll
    for (int mt = 0; mt < 2; mt++)
#pragma unroll
        for (int nt = 0; nt < NT; nt++)
#pragma unroll
            for (int e = 0; e < 4; e++) acc[mt][nt][e] = 0.f;

    auto stageA = [&](int c) {
        const uint32_t s = (uint32_t)(c & 1) * STAGE;
        const int kk0 = c * 64;
#pragma unroll
        for (int g = 0; g < 2; g++) {
            int t = tid + g * 256;
            int m = t >> 3, j = t & 7;
            uint32_t sw = SWZ((uint32_t)(m * 128 + j * 16));
            const size_t off = (size_t)(m0 + m) * Kp + kk0 + j * 8;
            cp16(sb + s + sw,          Ah + off, true);
            cp16(sb + s + ABYTES + sw, Al + off, true);
        }
    };
    auto stageB = [&](int c) {
        const uint32_t s = (uint32_t)(c & 1) * STAGE;
        const int kk0 = c * 64;
#pragma unroll
        for (int g = 0; g < 4; g++) {
            int t = tid + g * 256;
            int n = t >> 3, j = t & 7;
            bool ok = (n0 + n) < N;
            int row = ok ? (n0 + n) : 0;
            uint32_t sw = SWZ((uint32_t)(n * 128 + j * 16));
            const size_t off = (size_t)row * Kp + kk0 + j * 8;
            cp16(sb + s + 2 * ABYTES + sw,          Wh + off, ok);
            cp16(sb + s + 2 * ABYTES + BBYTES + sw, Wl + off, ok);
        }
    };

    const int qa = lane >> 3;
    const uint32_t rowA  = (uint32_t)(wm * 32 + (qa & 1) * 8 + (lane & 7));
    const uint32_t kaOff = (uint32_t)((qa >> 1) * 16);
    const uint32_t rowBp = (uint32_t)(wn * 32 + ((lane >> 4) & 1) * 8 + (lane & 7));
    const uint32_t kbOff = (uint32_t)(((lane >> 3) & 1) * 16);

    auto compute = [&](int c) {
        const uint32_t s = (uint32_t)(c & 1) * STAGE;
        const uint32_t bAh = sb + s, bAl = sb + s + ABYTES;
        const uint32_t bBh = sb + s + 2 * ABYTES, bBl = bBh + BBYTES;
#pragma unroll
        for (int s16 = 0; s16 < 4; s16++) {
            uint32_t a_h[2][4], a_l[2][4];
#pragma unroll
            for (int mt = 0; mt < 2; mt++) {
                uint32_t off = SWZ((rowA + mt * 16) * 128 + s16 * 32 + kaOff);
                ldsm_x4(a_h[mt], bAh + off);
                ldsm_x4(a_l[mt], bAl + off);
            }
            uint32_t b_h[NT][2], b_l[NT][2];
#pragma unroll
            for (int ntp = 0; ntp < NT / 2; ntp++) {
                uint32_t off = SWZ((rowBp + ntp * 16) * 128 + s16 * 32 + kbOff);
                uint32_t r4[4];
                ldsm_x4(r4, bBh + off);
                b_h[2 * ntp][0] = r4[0]; b_h[2 * ntp][1] = r4[1];
                b_h[2 * ntp + 1][0] = r4[2]; b_h[2 * ntp + 1][1] = r4[3];
                ldsm_x4(r4, bBl + off);
                b_l[2 * ntp][0] = r4[0]; b_l[2 * ntp][1] = r4[1];
                b_l[2 * ntp + 1][0] = r4[2]; b_l[2 * ntp + 1][1] = r4[3];
            }
#pragma unroll
            for (int mt = 0; mt < 2; mt++)
#pragma unroll
                for (int nt = 0; nt < NT; nt++) {
                    mma16816(acc[mt][nt], a_h[mt], b_h[nt]);
                    mma16816(acc[mt][nt], a_l[mt], b_h[nt]);
                    mma16816(acc[mt][nt], a_h[mt], b_l[nt]);
                }
        }
    };

    stageA(0); stageB(0); CP_COMMIT();

    for (int c = 0; c < nch; c++) {
        if (c + 1 < nch) {
            stageA(c + 1); stageB(c + 1); CP_COMMIT();
            CP_WAIT(1);
        } else {
            CP_WAIT(0);
        }
        __syncthreads();
        compute(c);
        __syncthreads();
    }

#pragma unroll
    for (int mt = 0; mt < 2; mt++) {
        int r0 = m0 + wm * 32 + mt * 16 + (lane >> 2);
#pragma unroll
        for (int nt = 0; nt < NT; nt++) {
            int col = n0 + wn * 32 + nt * 8 + (lane & 3) * 2;
            if (col >= N) continue;
            float2 bv = *(const float2*)(bias + col);
            float o0 = acc[mt][nt][0] + bv.x;
            float o1 = acc[mt][nt][1] + bv.y;
            float o2 = acc[mt][nt][2] + bv.x;
            float o3 = acc[mt][nt][3] + bv.y;
            if (relu) {
                o0 = fmaxf(o0, 0.f); o1 = fmaxf(o1, 0.f);
                o2 = fmaxf(o2, 0.f); o3 = fmaxf(o3, 0.f);
            }
            if (outf32) {
                *(float2*)(Cf + (size_t)r0 * N + col)       = make_float2(o0, o1);
                *(float2*)(Cf + (size_t)(r0 + 8) * N + col) = make_float2(o2, o3);
            } else {
                __nv_bfloat16 h0 = __float2bfloat16(o0);
                __nv_bfloat16 h1 = __float2bfloat16(o1);
                __nv_bfloat16 h2 = __float2bfloat16(o2);
                __nv_bfloat16 h3 = __float2bfloat16(o3);
                uint32_t hp0 = (uint32_t)__bfloat16_as_ushort(h0) |
                               ((uint32_t)__bfloat16_as_ushort(h1) << 16);
                uint32_t hp1 = (uint32_t)__bfloat16_as_ushort(h2) |
                               ((uint32_t)__bfloat16_as_ushort(h3) << 16);
                uint32_t lp0 = pack_bf16(o0 - __bfloat162float(h0),
                                         o1 - __bfloat162float(h1));
                uint32_t lp1 = pack_bf16(o2 - __bfloat162float(h2),
                                         o3 - __bfloat162float(h3));
                *(uint32_t*)(Ch + (size_t)r0 * N + col)       = hp0;
                *(uint32_t*)(Ch + (size_t)(r0 + 8) * N + col) = hp1;
                *(uint32_t*)(Cl + (size_t)r0 * N + col)       = lp0;
                *(uint32_t*)(Cl + (size_t)(r0 + 8) * N + col) = lp1;
            }
        }
    }
}

// ---------------- postproc (F precoder part only) ---------------------------
// out[:,200:264] = F * sqrt(2 / |F|^2). 64 threads per sample.
__global__ __launch_bounds__(64) void postproc_F(
    const float* __restrict__ t1, float* __restrict__ out)
{
    const int b   = blockIdx.x;
    const int tid = threadIdx.x;
    const float* row = t1 + (size_t)b * DOUT;

    __shared__ float s[2];

    int w = tid >> 5, l = tid & 31;
    {
        int base = 200 + 32 * w;   // 200 for F1, 232 for F2
        float v = 0.f;
        if (l < 16) {
            float re = row[base + l];
            float im = row[base + 16 + l];
            v = re * re + im * im;
        }
#pragma unroll
        for (int o = 8; o; o >>= 1) v += __shfl_down_sync(0xffffffffu, v, o);
        if (l == 0) s[w] = sqrtf(2.0f / v);
    }
    __syncthreads();

    int col = 200 + tid;
    float sc = (tid < 32) ? s[0] : s[1];
    out[(size_t)b * DOUT + col] = row[col] * sc;
}

// ---------------- quad pass 1: CCC[b][c] = Re(theta^H T_c theta)/thr --------
// theta normalized inline from t1 (no thetaN buffer).
__global__ __launch_bounds__(256) void quad_pass1(
    const float* __restrict__ Tr, const float* __restrict__ Ti,
    const float* __restrict__ t1, float* __restrict__ ccc)
{
    const int bc = blockIdx.x;
    const int b  = bc >> 2;
    const int tid = threadIdx.x;

    __shared__ float sa[100], sb_[100];
    __shared__ float da[4][32], db[4][32];   // da[e][q] = sa[4q+e]
    __shared__ float wsum[8];

    if (tid < 100) {
        const float* row = t1 + (size_t)b * DOUT;
        float re = row[tid];
        float im = row[100 + tid];
        float inv = rsqrtf(re * re + im * im);
        float a = re * inv, bb = im * inv;
        sa[tid] = a;  sb_[tid] = bb;
        da[tid & 3][tid >> 2] = a;
        db[tid & 3][tid >> 2] = bb;
    }
    __syncthreads();

    const float4* TrV = (const float4*)(Tr + (size_t)bc * 10000);
    const float4* TiV = (const float4*)(Ti + (size_t)bc * 10000);

    float acc = 0.f;
    for (int i = tid; i < 2500; i += 256) {
        int n = i / 25;
        int q = i - n * 25;
        float4 tr = __ldcs(TrV + i);
        float4 ti = __ldcs(TiV + i);
        float an = sa[n], bn = sb_[n];
        {
            float am = da[0][q], bm = db[0][q];
            acc += tr.x * (an * am + bn * bm) + ti.x * (bn * am - an * bm);
        }
        {
            float am = da[1][q], bm = db[1][q];
            acc += tr.y * (an * am + bn * bm) + ti.y * (bn * am - an * bm);
        }
        {
            float am = da[2][q], bm = db[2][q];
            acc += tr.z * (an * am + bn * bm) + ti.z * (bn * am - an * bm);
        }
        {
            float am = da[3][q], bm = db[3][q];
            acc += tr.w * (an * am + bn * bm) + ti.w * (bn * am - an * bm);
        }
    }

#pragma unroll
    for (int o = 16; o; o >>= 1) acc += __shfl_down_sync(0xffffffffu, acc, o);
    if ((tid & 31) == 0) wsum[tid >> 5] = acc;
    __syncthreads();
    if (tid == 0) {
        float s = 0.f;
#pragma unroll
        for (int w = 0; w < 8; w++) s += wsum[w];
        ccc[bc] = s * INV_THRESH;
    }
}

// ---------------- quad pass 2: scale + write theta_hat ----------------------
// Recomputes theta normalization from t1 (identical formula as pass1).
__global__ __launch_bounds__(128) void quad_pass2(
    const float* __restrict__ ccc, const float* __restrict__ t1,
    float* __restrict__ out)
{
    const int b = blockIdx.x;
    const int tid = threadIdx.x;
    float c0 = ccc[b * 4 + 0], c1 = ccc[b * 4 + 1];
    float c2 = ccc[b * 4 + 2], c3 = ccc[b * 4 + 3];
    float mx = fmaxf(fmaxf(c0, c1), fmaxf(c2, c3));
    float scale = rsqrtf(fmaxf(mx, 1.0f));
    if (tid < 100) {
        const float* row = t1 + (size_t)b * DOUT;
        float re = row[tid];
        float im = row[100 + tid];
        float inv = rsqrtf(re * re + im * im);
        out[(size_t)b * DOUT + tid]       = (re * inv) * scale;
        out[(size_t)b * DOUT + 100 + tid] = (im * inv) * scale;
    }
}

// ---------------- launch ----------------------------------------------------
extern "C" void kernel_launch(void* const* d_in, const int* in_sizes, int n_in,
                              void* d_out, int out_size)
{
    const float* X  = (const float*)d_in[0];
    const float* Tr = (const float*)d_in[1];
    const float* Ti = (const float*)d_in[2];
    const float* W1 = (const float*)d_in[3];
    const float* b1 = (const float*)d_in[4];
    const float* W2 = (const float*)d_in[5];
    const float* b2 = (const float*)d_in[6];
    const float* W3 = (const float*)d_in[7];
    const float* b3 = (const float*)d_in[8];
    const float* W4 = (const float*)d_in[9];
    const float* b4 = (const float*)d_in[10];
    float* out = (float*)d_out;

    float *t1, *ccc;
    cudaGetSymbolAddress((void**)&t1,  g_t1);
    cudaGetSymbolAddress((void**)&ccc, g_ccc);

    __nv_bfloat16 *xh, *xl, *h1h, *h1l, *h2h, *h2l, *h3h, *h3l;
    cudaGetSymbolAddress((void**)&xh,  g_Xh);
    cudaGetSymbolAddress((void**)&xl,  g_Xl);
    cudaGetSymbolAddress((void**)&h1h, g_h1h);
    cudaGetSymbolAddress((void**)&h1l, g_h1l);
    cudaGetSymbolAddress((void**)&h2h, g_h2h);
    cudaGetSymbolAddress((void**)&h2l, g_h2l);
    cudaGetSymbolAddress((void**)&h3h, g_h3h);
    cudaGetSymbolAddress((void**)&h3l, g_h3l);

    __nv_bfloat16 *w1h, *w1l, *w2h, *w2l, *w3h, *w3l, *w4h, *w4l;
    cudaGetSymbolAddress((void**)&w1h, g_W1h);
    cudaGetSymbolAddress((void**)&w1l, g_W1l);
    cudaGetSymbolAddress((void**)&w2h, g_W2h);
    cudaGetSymbolAddress((void**)&w2l, g_W2l);
    cudaGetSymbolAddress((void**)&w3h, g_W3h);
    cudaGetSymbolAddress((void**)&w3l, g_W3l);
    cudaGetSymbolAddress((void**)&w4h, g_W4h);
    cudaGetSymbolAddress((void**)&w4l, g_W4l);

    cudaFuncSetAttribute(gemm_mma, cudaFuncAttributeMaxDynamicSharedMemorySize,
                         SMEM_GEMM);

    prep_all<<<NB_TOTAL, 256>>>(X, W1, W2, W3, W4, xh, xl,
                                w1h, w1l, w2h, w2l, w3h, w3l, w4h, w4l);

    gemm_mma<<<dim3(D1 / 128, BATCH / 64), 256, SMEM_GEMM>>>(
        xh, xl, w1h, w1l, b1, nullptr, h1h, h1l, BATCH, D1, KP1, 1, 0);
    gemm_mma<<<dim3(D2 / 128, BATCH / 64), 256, SMEM_GEMM>>>(
        h1h, h1l, w2h, w2l, b2, nullptr, h2h, h2l, BATCH, D2, KP2, 1, 0);
    gemm_mma<<<dim3(D3 / 128, BATCH / 64), 256, SMEM_GEMM>>>(
        h2h, h2l, w3h, w3l, b3, nullptr, h3h, h3l, BATCH, D3, KP3, 1, 0);
    gemm_mma<<<dim3((DOUT + 127) / 128, BATCH / 64), 256, SMEM_GEMM>>>(
        h3h, h3l, w4h, w4l, b4, t1, nullptr, nullptr, BATCH, DOUT, KP4, 0, 1);

    postproc_F<<<BATCH, 64>>>(t1, out);
    quad_pass1<<<BATCH * NC, 256>>>(Tr, Ti, t1, ccc);
    quad_pass2<<<BATCH, 128>>>(ccc, t1, out);
}